// round 3
// baseline (speedup 1.0000x reference)
#include <cuda_runtime.h>
#include <cuda_fp16.h>
#include <cstdint>
#include <cstddef>

// ---------------- problem constants ----------------
static constexpr int Bb = 8;
static constexpr int Tt = 4096;
static constexpr int Dd = 1024;
static constexpr int Mm = Bb * Tt;      // 32768 rows
static constexpr int Kk = Dd;
static constexpr int Nn = Dd;

// GEMM tiling (HMMA mma.sync path — tcgen05 not available on this ptxas target)
static constexpr int TM = 128;
static constexpr int TN = 128;
static constexpr int TKI = 32;              // K per mainloop iter
static constexpr int KI = Kk / TKI;         // 32 iters
static constexpr int STAGES = 4;
static constexpr int PITCH_H = 40;          // halves per smem row (80 B: conflict-free)
static constexpr int STAGE_B = 128 * PITCH_H * 2;   // 10240 B per tile per stage
static constexpr int SMEM_DYN = STAGES * 2 * STAGE_B; // 81920 B

// scan chunking
static constexpr int Lc = 128;
static constexpr int Cc = Tt / Lc;          // 32 chunks per batch

// ---------------- device scratch (no allocs allowed) ----------------
__device__ __half g_xh[(size_t)Mm * Dd];
__device__ __half g_u [(size_t)Mm * Dd];
__device__ __half g_tr[(size_t)Mm * Dd];
__device__ __half g_win [Dd * Dd];
__device__ __half g_wout[Dd * Dd];
__device__ float  g_a[Dd];
__device__ float  g_S[Bb * Cc * Dd];
__device__ float  g_carry[Bb * Cc * Dd];

// ---------------- PTX helpers ----------------
#define DEV __device__ __forceinline__

DEV uint32_t s2u(const void* p) {
    uint32_t a;
    asm("{ .reg .u64 t; cvta.to.shared.u64 t, %1; cvt.u32.u64 %0, t; }"
        : "=r"(a) : "l"(p));
    return a;
}

DEV void cp16(uint32_t dst, const void* src) {
    asm volatile("cp.async.cg.shared.global [%0], [%1], 16;" :: "r"(dst), "l"(src));
}
#define CP_COMMIT() asm volatile("cp.async.commit_group;" ::: "memory")
#define CP_WAIT(n)  asm volatile("cp.async.wait_group %0;" :: "n"(n) : "memory")

DEV void ldm_x4(uint32_t* r, uint32_t addr) {
    asm volatile("ldmatrix.sync.aligned.m8n8.x4.shared.b16 {%0,%1,%2,%3}, [%4];"
                 : "=r"(r[0]), "=r"(r[1]), "=r"(r[2]), "=r"(r[3]) : "r"(addr));
}

DEV void mma16816(float* c, const uint32_t* a, uint32_t b0, uint32_t b1) {
    asm volatile(
        "mma.sync.aligned.m16n8k16.row.col.f32.f16.f16.f32 "
        "{%0,%1,%2,%3}, {%4,%5,%6,%7}, {%8,%9}, {%0,%1,%2,%3};"
        : "+f"(c[0]), "+f"(c[1]), "+f"(c[2]), "+f"(c[3])
        : "r"(a[0]), "r"(a[1]), "r"(a[2]), "r"(a[3]), "r"(b0), "r"(b1));
}

// ---------------- fused conversion kernel ----------------
// blocks [0, NXB): x -> fp16.  blocks [NXB, NXB+NWB): W_in/W_out -> fp16, tanh(a).
static constexpr int NXB = 4096;
static constexpr int NWB = 2048;
__global__ void conv_all_k(const float4* __restrict__ x4,
                           const float4* __restrict__ win4,
                           const float4* __restrict__ wout4,
                           const float* __restrict__ raw_a) {
    if (blockIdx.x < NXB) {
        size_t n = (size_t)Mm * Dd / 4;
        __half2* o = (__half2*)g_xh;
        for (size_t i = (size_t)blockIdx.x * blockDim.x + threadIdx.x; i < n;
             i += (size_t)NXB * blockDim.x) {
            float4 v = x4[i];
            o[2 * i]     = __floats2half2_rn(v.x, v.y);
            o[2 * i + 1] = __floats2half2_rn(v.z, v.w);
        }
    } else {
        int i = (blockIdx.x - NXB) * blockDim.x + threadIdx.x;
        const int q = Dd * Dd / 4;
        if (i < q) {
            float4 v = win4[i];
            __half2* wi = (__half2*)g_win;
            wi[2 * i]     = __floats2half2_rn(v.x, v.y);
            wi[2 * i + 1] = __floats2half2_rn(v.z, v.w);
        } else if (i < 2 * q) {
            int j = i - q;
            float4 v = wout4[j];
            __half2* wo = (__half2*)g_wout;
            wo[2 * j]     = __floats2half2_rn(v.x, v.y);
            wo[2 * j + 1] = __floats2half2_rn(v.z, v.w);
        }
        if (i < Dd) g_a[i] = tanhf(raw_a[i]);
    }
}

// ---------------- HMMA GEMM: C[M,N] = A[M,K] * W[N,K]^T ----------------
// PHASE 0: A=g_xh, W=g_win, C=g_u (fp16).  PHASE 1: A=g_tr, W=g_wout, C=outp (fp32).
DEV void fill_stage(int tid, int s, int kIter, uint32_t smem0,
                    const __half* Aa, const __half* Bw, int m0, int n0) {
    int k0 = kIter * TKI;
    uint32_t aS = smem0 + s * STAGE_B;
    uint32_t bS = smem0 + STAGES * STAGE_B + s * STAGE_B;
    // A: 128 rows x 32 halves = 512 x 16B chunks; 256 threads x 2
#pragma unroll
    for (int h = 0; h < 2; h++) {
        int q = tid + h * 256;
        int row = q >> 2, c = q & 3;
        cp16(aS + row * (PITCH_H * 2) + c * 16,
             Aa + (size_t)(m0 + row) * Kk + k0 + c * 8);
    }
#pragma unroll
    for (int h = 0; h < 2; h++) {
        int q = tid + h * 256;
        int row = q >> 2, c = q & 3;
        cp16(bS + row * (PITCH_H * 2) + c * 16,
             Bw + (size_t)(n0 + row) * Kk + k0 + c * 8);
    }
}

template <int PHASE>
__global__ void __launch_bounds__(256, 2) gemm_f16_k(float* __restrict__ outp) {
    extern __shared__ __align__(16) char smem_raw[];
    const __half* Aa = PHASE ? g_tr : g_xh;
    const __half* Bw = PHASE ? g_wout : g_win;

    int tid = threadIdx.x;
    int w = tid >> 5, lane = tid & 31;
    int wm = (w & 3) * 32;      // warp M offset (4 warps along M)
    int wn = (w >> 2) * 64;     // warp N offset (2 warps along N)
    int m0 = (blockIdx.x >> 3) * TM;
    int n0 = (blockIdx.x & 7) * TN;

    uint32_t smem0 = s2u(smem_raw);

    float acc[2][8][4];
#pragma unroll
    for (int i = 0; i < 2; i++)
#pragma unroll
        for (int j = 0; j < 8; j++)
#pragma unroll
            for (int v = 0; v < 4; v++) acc[i][j][v] = 0.f;

    // prologue: fill STAGES-1 stages
#pragma unroll
    for (int p = 0; p < STAGES - 1; p++) {
        fill_stage(tid, p, p, smem0, Aa, Bw, m0, n0);
        CP_COMMIT();
    }

    // precomputed ldmatrix lane addresses (within a stage, kg=0)
    // A: row = wm + mt*16 + lane%16, khalf = lane/16
    uint32_t aAddr = (uint32_t)((wm + (lane & 15)) * (PITCH_H * 2) + (lane >> 4) * 16);
    // B: n = wn + nt4*16 + (lane/16)*8 + lane%8, khalf = (lane>>3)&1
    uint32_t bAddr = (uint32_t)((wn + (lane >> 4) * 8 + (lane & 7)) * (PITCH_H * 2)
                                + ((lane >> 3) & 1) * 16);
    uint32_t bTileStride = 16 * (PITCH_H * 2);   // n += 16

    for (int k = 0; k < KI; k++) {
        int s = k % STAGES;
        CP_WAIT(STAGES - 2);
        __syncthreads();
        int kn = k + STAGES - 1;
        if (kn < KI) fill_stage(tid, kn % STAGES, kn, smem0, Aa, Bw, m0, n0);
        CP_COMMIT();

        uint32_t aS = smem0 + s * STAGE_B;
        uint32_t bS = smem0 + STAGES * STAGE_B + s * STAGE_B;
#pragma unroll
        for (int kg = 0; kg < 2; kg++) {            // two k16 groups per stage
            uint32_t a[2][4], b[4][4];
#pragma unroll
            for (int mt = 0; mt < 2; mt++)
                ldm_x4(a[mt], aS + aAddr + mt * (16 * PITCH_H * 2) + kg * 32);
#pragma unroll
            for (int nt4 = 0; nt4 < 4; nt4++)
                ldm_x4(b[nt4], bS + bAddr + nt4 * bTileStride + kg * 32);
#pragma unroll
            for (int mt = 0; mt < 2; mt++)
#pragma unroll
                for (int nt = 0; nt < 8; nt++)
                    mma16816(acc[mt][nt], a[mt],
                             b[nt >> 1][(nt & 1) * 2], b[nt >> 1][(nt & 1) * 2 + 1]);
        }
    }

    // epilogue: direct gmem stores
#pragma unroll
    for (int mt = 0; mt < 2; mt++) {
        int r0 = m0 + wm + mt * 16 + (lane >> 2);
#pragma unroll
        for (int nt = 0; nt < 8; nt++) {
            int col = n0 + wn + nt * 8 + (lane & 3) * 2;
            if (PHASE == 0) {
                *(__half2*)(g_u + (size_t)r0 * Nn + col) =
                    __floats2half2_rn(acc[mt][nt][0], acc[mt][nt][1]);
                *(__half2*)(g_u + (size_t)(r0 + 8) * Nn + col) =
                    __floats2half2_rn(acc[mt][nt][2], acc[mt][nt][3]);
            } else {
                *(float2*)(outp + (size_t)r0 * Nn + col) =
                    make_float2(acc[mt][nt][0], acc[mt][nt][1]);
                *(float2*)(outp + (size_t)(r0 + 8) * Nn + col) =
                    make_float2(acc[mt][nt][2], acc[mt][nt][3]);
            }
        }
    }
}

// ---------------- scan kernels (3-phase chunked) ----------------
__global__ void scan_partial_k() {
    int bc = blockIdx.x;
    int b = bc / Cc, c = bc % Cc;
    int d2 = threadIdx.x;
    float a0 = g_a[2 * d2], a1 = g_a[2 * d2 + 1];
    const __half2* up = (const __half2*)g_u
        + ((size_t)(b * Tt + c * Lc)) * (Dd / 2) + d2;
    float s0 = 0.f, s1 = 0.f;
#pragma unroll 4
    for (int i = 0; i < Lc; i++) {
        float2 u = __half22float2(up[(size_t)i * (Dd / 2)]);
        s0 = fmaf(a0, s0, u.x);
        s1 = fmaf(a1, s1, u.y);
    }
    float* S = g_S + (size_t)bc * Dd;
    S[2 * d2] = s0;
    S[2 * d2 + 1] = s1;
}

__global__ void scan_carry_k(const float* __restrict__ h0) {
    int b = blockIdx.x;
    int d = threadIdx.x;
    float a = g_a[d];
    float aL = a;
#pragma unroll
    for (int i = 0; i < 7; i++) aL *= aL;   // a^128
    float H = h0[b * Dd + d];
    for (int c = 0; c < Cc; c++) {
        size_t idx = ((size_t)b * Cc + c) * Dd + d;
        g_carry[idx] = H;
        H = fmaf(aL, H, g_S[idx]);
    }
}

__global__ void scan_traj_k(float* __restrict__ hlast) {
    int bc = blockIdx.x;
    int b = bc / Cc, c = bc % Cc;
    int d2 = threadIdx.x;
    float a0 = g_a[2 * d2], a1 = g_a[2 * d2 + 1];
    float h0v = g_carry[(size_t)bc * Dd + 2 * d2];
    float h1v = g_carry[(size_t)bc * Dd + 2 * d2 + 1];
    size_t base = ((size_t)(b * Tt + c * Lc)) * (Dd / 2) + d2;
    const __half2* up = (const __half2*)g_u + base;
    __half2* tp = (__half2*)g_tr + base;
#pragma unroll 4
    for (int i = 0; i < Lc; i++) {
        float2 u = __half22float2(up[(size_t)i * (Dd / 2)]);
        h0v = fmaf(a0, h0v, u.x);
        h1v = fmaf(a1, h1v, u.y);
        tp[(size_t)i * (Dd / 2)] = __floats2half2_rn(h0v, h1v);
    }
    if (c == Cc - 1) {
        hlast[b * Dd + 2 * d2] = h0v;
        hlast[b * Dd + 2 * d2 + 1] = h1v;
    }
}

// ---------------- launch ----------------
extern "C" void kernel_launch(void* const* d_in, const int* in_sizes, int n_in,
                              void* d_out, int out_size) {
    const float* x     = (const float*)d_in[0];
    const float* h0    = (const float*)d_in[1];
    const float* raw_a = (const float*)d_in[2];
    const float* W_in  = (const float*)d_in[3];
    const float* W_out = (const float*)d_in[4];
    float* out   = (float*)d_out;
    float* hlast = out + (size_t)Mm * Dd;

    cudaFuncSetAttribute(gemm_f16_k<0>, cudaFuncAttributeMaxDynamicSharedMemorySize, SMEM_DYN);
    cudaFuncSetAttribute(gemm_f16_k<1>, cudaFuncAttributeMaxDynamicSharedMemorySize, SMEM_DYN);

    conv_all_k<<<NXB + NWB, 256>>>((const float4*)x, (const float4*)W_in,
                                   (const float4*)W_out, raw_a);

    gemm_f16_k<0><<<(Mm / TM) * (Nn / TN), 256, SMEM_DYN>>>(nullptr);   // u = x W_in^T

    scan_partial_k<<<Bb * Cc, Dd / 2>>>();
    scan_carry_k<<<Bb, Dd>>>(h0);
    scan_traj_k<<<Bb * Cc, Dd / 2>>>(hlast);

    gemm_f16_k<1><<<(Mm / TM) * (Nn / TN), 256, SMEM_DYN>>>(out);       // out = traj W_out^T
}